// round 4
// baseline (speedup 1.0000x reference)
#include <cuda_runtime.h>

typedef unsigned long long u64;

// ---------------- static scratch (no runtime allocation) ----------------
#define MAXPTS  (1 << 21)        // 2M points max
#define LBITS   15               // morton(5,5,5) for 32^3 lev2 grid
#define MAXB    8
#define NBINS   (MAXB << LBITS)  // 262144 bins

__device__ int g_perm[MAXPTS];
__device__ int g_hist[NBINS];
__device__ int g_off[NBINS];

// ---- packed f32x2 helpers (Blackwell; ptxas won't auto-fuse) ----
static __device__ __forceinline__ u64 pack2(float v) {
    u64 r; asm("mov.b64 %0, {%1, %1};" : "=l"(r) : "f"(v)); return r;
}
static __device__ __forceinline__ u64 mul2(u64 a, u64 b) {
    u64 r; asm("mul.rn.f32x2 %0, %1, %2;" : "=l"(r) : "l"(a), "l"(b)); return r;
}
static __device__ __forceinline__ u64 fma2(u64 a, u64 b, u64 c) {
    u64 r; asm("fma.rn.f32x2 %0, %1, %2, %3;" : "=l"(r) : "l"(a), "l"(b), "l"(c)); return r;
}
struct P4 { u64 a, b; };
static __device__ __forceinline__ P4 ld4(const float4* __restrict__ p) {
    ulonglong2 u = *reinterpret_cast<const ulonglong2*>(p);
    P4 r; r.a = u.x; r.b = u.y; return r;
}
static __device__ __forceinline__ P4 lerp4p(P4 A, P4 B, u64 WA, u64 WB) {
    P4 r;
    r.a = fma2(A.a, WA, mul2(B.a, WB));
    r.b = fma2(A.b, WA, mul2(B.b, WB));
    return r;
}

// ---------------- sort-by-lev2-Morton-cell pipeline ----------------
static __device__ __forceinline__ unsigned morton5(unsigned x, unsigned y, unsigned z) {
    unsigned m = 0;
#pragma unroll
    for (int i = 0; i < 5; i++)
        m |= (((x >> i) & 1u) << (3 * i + 2)) |
             (((y >> i) & 1u) << (3 * i + 1)) |
             (((z >> i) & 1u) << (3 * i + 0));
    return m;
}

static __device__ __forceinline__ unsigned point_key(
    const float* __restrict__ coords, int point, int b)
{
    float cx = coords[point * 3 + 0];
    float cy = coords[point * 3 + 1];
    float cz = coords[point * 3 + 2];
    float ix = fminf(fmaxf(cx * 32.0f, 0.01f), 30.99f);
    float iy = fminf(fmaxf(cy * 32.0f, 0.01f), 30.99f);
    float iz = fminf(fmaxf(cz * 32.0f, 0.01f), 30.99f);
    return ((unsigned)b << LBITS) |
           morton5((unsigned)(int)floorf(ix), (unsigned)(int)floorf(iy),
                   (unsigned)(int)floorf(iz));
}

__global__ void zero_hist_kernel() {
    int i = blockIdx.x * 1024 + threadIdx.x;
    if (i < NBINS) g_hist[i] = 0;
}

__global__ void hist_kernel(const float* __restrict__ coords, int BN, int Npts) {
    int p = blockIdx.x * 256 + threadIdx.x;
    if (p >= BN) return;
    int b = (unsigned)p / (unsigned)Npts;
    atomicAdd(&g_hist[point_key(coords, p, b)], 1);
}

// Single-block exclusive scan over NBINS: 1024 threads x 256 bins each.
__global__ void scan_kernel() {
    __shared__ int sh[1024];
    int tid = threadIdx.x;
    int base = tid * (NBINS / 1024);
    int local = 0;
#pragma unroll 4
    for (int i = 0; i < NBINS / 1024; i++) local += g_hist[base + i];
    sh[tid] = local;
    __syncthreads();
    // Kogge-Stone inclusive scan
    for (int d = 1; d < 1024; d <<= 1) {
        int v = (tid >= d) ? sh[tid - d] : 0;
        __syncthreads();
        sh[tid] += v;
        __syncthreads();
    }
    int run = sh[tid] - local;  // exclusive prefix for this thread's chunk
    for (int i = 0; i < NBINS / 1024; i++) {
        g_off[base + i] = run;
        run += g_hist[base + i];
    }
}

__global__ void scatter_kernel(const float* __restrict__ coords, int BN, int Npts) {
    int p = blockIdx.x * 256 + threadIdx.x;
    if (p >= BN) return;
    int b = (unsigned)p / (unsigned)Npts;
    int pInB = p - b * Npts;
    int pos = atomicAdd(&g_off[point_key(coords, p, b)], 1);
    g_perm[pos] = (b << 28) | pInB;   // pack: no division in main kernel
}

// ---------------- main sampling kernel ----------------
// Levels 1 (64^3 x 32), 2 (32^3 x 64), 3 (16^3 x 128); out 227 floats/point.
// 64 threads/point, 4 ch/thread; block 512 = 8 spatially-sorted points -> L1 reuse.
__global__ void __launch_bounds__(512) trilerp_kernel(
    const float* __restrict__ f1, const float* __restrict__ f2, const float* __restrict__ f3,
    const float* __restrict__ coords, const float* __restrict__ meshf,
    float* __restrict__ out, int BN, int Npts)
{
    int t = blockIdx.x * 512 + threadIdx.x;
    int gpSlot = t >> 6;
    if (gpSlot >= BN) return;
    int slot = t & 63;

    int val = g_perm[gpSlot];
    int b = val >> 28;
    int point = b * Npts + (val & 0x0FFFFFFF);
    size_t obase = (size_t)point * 227;

    if (slot >= 56) {
        int k = slot - 56;
        if (k < 3) out[obase + 224 + k] = __ldg(meshf + point * 3 + k);
        return;
    }

    float cx = __ldg(coords + point * 3 + 0);
    float cy = __ldg(coords + point * 3 + 1);
    float cz = __ldg(coords + point * 3 + 2);

    int lev = (slot < 8) ? 1 : ((slot < 24) ? 2 : 3);
    const float4* __restrict__ fp =
        (const float4*)((lev == 1) ? f1 : ((lev == 2) ? f2 : f3));
    int cstart = (lev == 1) ? 0 : ((lev == 2) ? 8 : 24);
    int R  = 128 >> lev;         // 64 / 32 / 16
    int s4 = 4 << lev;           // C/4 = 8 / 16 / 32
    int c4 = slot - cstart;      // channel base in float4 units

    float scale = (float)R;
    float hi = scale - 1.01f;
    float ix = fminf(fmaxf(cx * scale, 0.01f), hi);
    float iy = fminf(fmaxf(cy * scale, 0.01f), hi);
    float iz = fminf(fmaxf(cz * scale, 0.01f), hi);

    float fx1 = floorf(ix), fx2 = ceilf(ix);
    float fy1 = floorf(iy), fy2 = ceilf(iy);
    float fz1 = floorf(iz), fz2 = ceilf(iz);

    u64 WX = pack2(ix - fx1), WX2 = pack2(fx2 - ix);
    u64 WY = pack2(iy - fy1), WY2 = pack2(fy2 - iy);
    u64 WZ = pack2(iz - fz1), WZ2 = pack2(fz2 - iz);

    int x1 = (int)fx1, y1 = (int)fy1, z1 = (int)fz1;
    int dxs = ((int)fx2 - x1) * R * R * s4;
    int dys = ((int)fy2 - y1) * R * s4;
    int dzs = ((int)fz2 - z1) * s4;
    const float4* p = fp + (((b * R + x1) * R + y1) * R + z1) * s4 + c4;

    P4 v111 = ld4(p);
    P4 v211 = ld4(p + dxs);
    P4 v121 = ld4(p + dys);
    P4 v221 = ld4(p + dxs + dys);
    P4 v112 = ld4(p + dzs);
    P4 v212 = ld4(p + dxs + dzs);
    P4 v122 = ld4(p + dys + dzs);
    P4 v222 = ld4(p + dxs + dys + dzs);

    P4 la = lerp4p(v211, v111, WX, WX2);
    P4 lb = lerp4p(v221, v121, WX, WX2);
    P4 l1 = lerp4p(lb, la, WY, WY2);
    P4 lc = lerp4p(v212, v112, WX, WX2);
    P4 ld_ = lerp4p(v222, v122, WX, WX2);
    P4 l2 = lerp4p(ld_, lc, WY, WY2);
    P4 r  = lerp4p(l2, l1, WZ, WZ2);

    // alignment class is warp-uniform (one point per half-warp group of 64)
    unsigned omod = (unsigned)(obase & 3);
    float* q = out + obase + 4 * slot;
    if (omod == 0) {
        *reinterpret_cast<ulonglong2*>(q) = make_ulonglong2(r.a, r.b);   // STG.128
    } else if ((omod & 1) == 0) {
        reinterpret_cast<u64*>(q)[0] = r.a;                              // 2x STG.64
        reinterpret_cast<u64*>(q)[1] = r.b;
    } else {
        float a0, a1, b0, b1;
        asm("mov.b64 {%0,%1}, %2;" : "=f"(a0), "=f"(a1) : "l"(r.a));
        asm("mov.b64 {%0,%1}, %2;" : "=f"(b0), "=f"(b1) : "l"(r.b));
        q[0] = a0; q[1] = a1; q[2] = b0; q[3] = b1;
    }
}

extern "C" void kernel_launch(void* const* d_in, const int* in_sizes, int n_in,
                              void* d_out, int out_size)
{
    // metadata order: features0..features4, mesh_coords, mesh_features
    const float* f1     = (const float*)d_in[1];
    const float* f2     = (const float*)d_in[2];
    const float* f3     = (const float*)d_in[3];
    const float* coords = (const float*)d_in[5];
    const float* meshf  = (const float*)d_in[6];
    float* out = (float*)d_out;

    int B    = in_sizes[1] / (64 * 64 * 64 * 32);
    int BN   = in_sizes[5] / 3;
    int Npts = BN / B;

    // 1) counting sort of point ids by (batch, lev2 Morton cell)
    zero_hist_kernel<<<(NBINS + 1023) / 1024, 1024>>>();
    hist_kernel<<<(BN + 255) / 256, 256>>>(coords, BN, Npts);
    scan_kernel<<<1, 1024>>>();
    scatter_kernel<<<(BN + 255) / 256, 256>>>(coords, BN, Npts);

    // 2) sampling in sorted order (output written by original index)
    long long tpb = (long long)BN * 64;
    int blocks = (int)((tpb + 511) / 512);
    trilerp_kernel<<<blocks, 512>>>(f1, f2, f3, coords, meshf, out, BN, Npts);
}

// round 5
// speedup vs baseline: 9.1024x; 9.1024x over previous
#include <cuda_runtime.h>

typedef unsigned long long u64;

// ---- packed f32x2 helpers (Blackwell; ptxas won't auto-fuse) ----
static __device__ __forceinline__ u64 pack2(float v) {
    u64 r; asm("mov.b64 %0, {%1, %1};" : "=l"(r) : "f"(v)); return r;
}
static __device__ __forceinline__ u64 mul2(u64 a, u64 b) {
    u64 r; asm("mul.rn.f32x2 %0, %1, %2;" : "=l"(r) : "l"(a), "l"(b)); return r;
}
static __device__ __forceinline__ u64 fma2(u64 a, u64 b, u64 c) {
    u64 r; asm("fma.rn.f32x2 %0, %1, %2, %3;" : "=l"(r) : "l"(a), "l"(b), "l"(c)); return r;
}
struct P4 { u64 a, b; };

// Forced 8-byte global load (keeps LDG.64; independent loads pipeline at the
// ~1.0 cyc/wavefront cross-LDG L1 rate instead of ~2.07 within-LDG replay rate)
static __device__ __forceinline__ u64 ldg64(const u64* p) {
    u64 r; asm("ld.global.nc.b64 %0, [%1];" : "=l"(r) : "l"(p)); return r;
}
static __device__ __forceinline__ P4 ld4s(const float4* __restrict__ p) {
    const u64* q = (const u64*)p;
    P4 r; r.a = ldg64(q); r.b = ldg64(q + 1); return r;
}
// A*WA + B*WB componentwise
static __device__ __forceinline__ P4 lerp4p(P4 A, P4 B, u64 WA, u64 WB) {
    P4 r;
    r.a = fma2(A.a, WA, mul2(B.a, WB));
    r.b = fma2(A.b, WA, mul2(B.b, WB));
    return r;
}

// ---- streaming (evict-first) stores: keep output out of L2 so the feature
// grids (~78MB) stay resident ----
static __device__ __forceinline__ void st128cs(float* p, u64 a, u64 b) {
    asm volatile("st.global.cs.v2.u64 [%0], {%1, %2};" :: "l"(p), "l"(a), "l"(b));
}
static __device__ __forceinline__ void st64cs(float* p, u64 a) {
    asm volatile("st.global.cs.u64 [%0], %1;" :: "l"(p), "l"(a));
}
static __device__ __forceinline__ void st32cs(float* p, float a) {
    asm volatile("st.global.cs.f32 [%0], %1;" :: "l"(p), "f"(a));
}

// Multi-res trilinear sampling. Levels 1 (64^3x32), 2 (32^3x64), 3 (16^3x128).
// Out per point: [32 | 64 | 128 | mesh 3] = 227 floats.
// 64 threads/point, 4 channels/thread:
//   slot 0..7 -> lev1, 8..23 -> lev2, 24..55 -> lev3, 56..58 -> mesh.
// Global out channel = 4*slot for slots 0..55 (concat offsets align).
__global__ void __launch_bounds__(256) trilerp_kernel(
    const float* __restrict__ f1, const float* __restrict__ f2, const float* __restrict__ f3,
    const float* __restrict__ coords, const float* __restrict__ meshf,
    float* __restrict__ out, int Npts)
{
    int t = blockIdx.x * 256 + threadIdx.x;
    int pInB = t >> 6;
    if (pInB >= Npts) return;
    int slot = t & 63;
    int b = blockIdx.y;
    int point = b * Npts + pInB;
    size_t obase = (size_t)point * 227;

    if (slot >= 56) {
        int k = slot - 56;
        if (k < 3) st32cs(out + obase + 224 + k, __ldg(meshf + point * 3 + k));
        return;
    }

    float cx = __ldg(coords + point * 3 + 0);
    float cy = __ldg(coords + point * 3 + 1);
    float cz = __ldg(coords + point * 3 + 2);

    int lev = (slot < 8) ? 1 : ((slot < 24) ? 2 : 3);
    const float4* __restrict__ fp =
        (const float4*)((lev == 1) ? f1 : ((lev == 2) ? f2 : f3));
    int cstart = (lev == 1) ? 0 : ((lev == 2) ? 8 : 24);
    int R  = 128 >> lev;         // 64 / 32 / 16
    int s4 = 4 << lev;           // C/4 = 8 / 16 / 32
    int c4 = slot - cstart;      // channel base in float4 units

    float scale = (float)R;      // 0.5^lev * 128 == R
    float hi = scale - 1.01f;
    float ix = fminf(fmaxf(cx * scale, 0.01f), hi);
    float iy = fminf(fmaxf(cy * scale, 0.01f), hi);
    float iz = fminf(fmaxf(cz * scale, 0.01f), hi);

    float fx1 = floorf(ix), fx2 = ceilf(ix);
    float fy1 = floorf(iy), fy2 = ceilf(iy);
    float fz1 = floorf(iz), fz2 = ceilf(iz);

    u64 WX = pack2(ix - fx1), WX2 = pack2(fx2 - ix);
    u64 WY = pack2(iy - fy1), WY2 = pack2(fy2 - iy);
    u64 WZ = pack2(iz - fz1), WZ2 = pack2(fz2 - iz);

    int x1 = (int)fx1, y1 = (int)fy1, z1 = (int)fz1;
    // corner step offsets (0 or one full stride) in float4 units
    int dxs = ((int)fx2 - x1) * R * R * s4;
    int dys = ((int)fy2 - y1) * R * s4;
    int dzs = ((int)fz2 - z1) * s4;
    const float4* p = fp + (((b * R + x1) * R + y1) * R + z1) * s4 + c4;

    // 16 independent LDG.64s, front-batched
    P4 v111 = ld4s(p);
    P4 v211 = ld4s(p + dxs);
    P4 v121 = ld4s(p + dys);
    P4 v221 = ld4s(p + dxs + dys);
    P4 v112 = ld4s(p + dzs);
    P4 v212 = ld4s(p + dxs + dzs);
    P4 v122 = ld4s(p + dys + dzs);
    P4 v222 = ld4s(p + dxs + dys + dzs);

    // z = z1 plane
    P4 la = lerp4p(v211, v111, WX, WX2);
    P4 lb = lerp4p(v221, v121, WX, WX2);
    P4 l1 = lerp4p(lb, la, WY, WY2);
    // z = z2 plane
    P4 lc = lerp4p(v212, v112, WX, WX2);
    P4 ld_ = lerp4p(v222, v122, WX, WX2);
    P4 l2 = lerp4p(ld_, lc, WY, WY2);

    P4 r = lerp4p(l2, l1, WZ, WZ2);

    // out alignment class is warp-uniform (4*slot ≡ 0 mod 4; obase mod 4 fixed per point)
    unsigned omod = (unsigned)(obase & 3);
    float* q = out + obase + 4 * slot;
    if (omod == 0) {
        st128cs(q, r.a, r.b);                 // STG.128
    } else if ((omod & 1) == 0) {
        st64cs(q, r.a);                       // 2x STG.64
        st64cs(q + 2, r.b);
    } else {
        float a0, a1, b0, b1;
        asm("mov.b64 {%0,%1}, %2;" : "=f"(a0), "=f"(a1) : "l"(r.a));
        asm("mov.b64 {%0,%1}, %2;" : "=f"(b0), "=f"(b1) : "l"(r.b));
        st32cs(q + 0, a0); st32cs(q + 1, a1);
        st32cs(q + 2, b0); st32cs(q + 3, b1);
    }
}

extern "C" void kernel_launch(void* const* d_in, const int* in_sizes, int n_in,
                              void* d_out, int out_size)
{
    // metadata order: features0..features4, mesh_coords, mesh_features
    const float* f1     = (const float*)d_in[1];
    const float* f2     = (const float*)d_in[2];
    const float* f3     = (const float*)d_in[3];
    const float* coords = (const float*)d_in[5];
    const float* meshf  = (const float*)d_in[6];
    float* out = (float*)d_out;

    int B    = in_sizes[1] / (64 * 64 * 64 * 32);
    int BN   = in_sizes[5] / 3;
    int Npts = BN / B;

    long long tpb = (long long)Npts * 64;
    dim3 grid((unsigned)((tpb + 255) / 256), (unsigned)B);
    trilerp_kernel<<<grid, 256>>>(f1, f2, f3, coords, meshf, out, Npts);
}